// round 12
// baseline (speedup 1.0000x reference)
#include <cuda_runtime.h>
#include <cuda_fp16.h>
#include <cstdint>
#include <math.h>

#define BD 32
#define TD 512
#define SD 1024
#define DD 1024

typedef __half h16;

// ---------------- scratch (device globals; no runtime allocation) ----------------
__device__ h16 g_in_hi [(size_t)BD*TD*DD],   g_in_lo [(size_t)BD*TD*DD];
__device__ h16 g_ctx_hi[(size_t)BD*SD*DD],   g_ctx_lo[(size_t)BD*SD*DD];
__device__ h16 g_ctxT_hi[(size_t)BD*DD*SD],  g_ctxT_lo[(size_t)BD*DD*SD];
__device__ h16 g_win_hi[(size_t)DD*DD],      g_win_lo[(size_t)DD*DD];
__device__ h16 g_wout_hi[(size_t)DD*2*DD],   g_wout_lo[(size_t)DD*2*DD];
__device__ h16 g_h_hi  [(size_t)BD*TD*DD],   g_h_lo  [(size_t)BD*TD*DD];
__device__ h16 g_av_hi [(size_t)TD*BD*SD];
__device__ h16 g_cc_hi [(size_t)TD*BD*2*DD];
__device__ float g_cbuf[(size_t)TD*BD*DD];   // GEMM6a partial (input @ Wout_i^T)

// ---------------- PTX helpers ----------------
__device__ __forceinline__ uint32_t smem_u32(const void* p) {
    uint32_t a;
    asm("{ .reg .u64 t; cvta.to.shared.u64 t, %1; cvt.u32.u64 %0, t; }" : "=r"(a) : "l"(p));
    return a;
}
__device__ __forceinline__ void cp16(uint32_t dst, const void* src) {
    asm volatile("cp.async.cg.shared.global [%0], [%1], 16;\n" :: "r"(dst), "l"(src) : "memory");
}
#define CP_COMMIT() asm volatile("cp.async.commit_group;\n" ::: "memory")
#define CP_WAIT(n)  asm volatile("cp.async.wait_group %0;\n" :: "n"(n) : "memory")
#define SW128(o)    ((o) ^ (((o) >> 3) & 0x70))

__device__ __forceinline__ void ldsm4(uint32_t* r, uint32_t addr) {
    asm volatile("ldmatrix.sync.aligned.m8n8.x4.shared.b16 {%0,%1,%2,%3}, [%4];"
                 : "=r"(r[0]), "=r"(r[1]), "=r"(r[2]), "=r"(r[3]) : "r"(addr));
}
__device__ __forceinline__ void mma16816(float* c, const uint32_t* a, const uint32_t* b) {
    asm volatile(
        "mma.sync.aligned.m16n8k16.row.col.f32.f16.f16.f32 "
        "{%0,%1,%2,%3}, {%4,%5,%6,%7}, {%8,%9}, {%0,%1,%2,%3};"
        : "+f"(c[0]), "+f"(c[1]), "+f"(c[2]), "+f"(c[3])
        : "r"(a[0]), "r"(a[1]), "r"(a[2]), "r"(a[3]), "r"(b[0]), "r"(b[1]));
}
__device__ __forceinline__ void split2(float a, float b, __half2& H, __half2& L) {
    __half ha = __float2half_rn(a), hb = __float2half_rn(b);
    H = __halves2half2(ha, hb);
    L = __halves2half2(__float2half_rn(a - __half2float(ha)),
                       __float2half_rn(b - __half2float(hb)));
}
__device__ __forceinline__ __half2 pack2(float a, float b) {
    return __halves2half2(__float2half_rn(a), __float2half_rn(b));
}

// ---------------- fp16-split HMMA GEMM, occupancy-2, single-sync mainloop ----------------
// C[m,n] = sum_k A[m,k]*B[n,k] (NT). B fp16 (hi,lo) pair of fp32.
// TERMS=3: A (hi,lo) pair, Ah*Bh + Ah*Bl + Al*Bh.  TERMS=2: A hi only, Ah*(Bh+Bl).
// CTA 128x128, warp tile 64x32 (8 warps as 2Mx4N). K-chunk 32, [hi|lo] packed per
// 128B row; stage 32KB; 3-stage cp.async pipeline; 2 CTAs/SM. LOADC: acc init Cin.
// WPAIR: emit fp16 hi; WLO additionally emit fp16 lo (fp32 residual).
static constexpr int ST_BYTES = 32768;           // A 16K (hi|lo slots) + B 16K
static constexpr int SMEM_TOT = 3 * ST_BYTES;    // 96 KB -> 2 CTAs/SM

template <int TERMS, int K, bool WF32, bool WTANH, bool WPAIR, bool WLO, bool LOADC>
__global__ void __launch_bounds__(256, 2) gemm_hmma(
    const h16* __restrict__ Ahi_, const h16* __restrict__ Alo_,
    long long lda, long long sA,
    const h16* __restrict__ Bhi_, const h16* __restrict__ Blo_,
    long long ldb, long long sB,
    float* __restrict__ C_, long long ldc, long long sC,
    h16* __restrict__ Phi_, h16* __restrict__ Plo_,
    long long ldp, long long sP,
    const float* __restrict__ Cin_)
{
    extern __shared__ char smem[];
    const uint32_t sb = smem_u32(smem);
    const int tid = threadIdx.x, wid = tid >> 5, l = tid & 31;
    const long long bz = blockIdx.z;
    const h16* Ahi = Ahi_ + bz * sA;
    const h16* Alo = Alo_ + bz * sA;
    const h16* Bhi = Bhi_ + bz * sB;
    const h16* Blo = Blo_ + bz * sB;
    const long long m0 = (long long)blockIdx.y * 128;
    const long long n0 = (long long)blockIdx.x * 128;

    const int wm = wid & 1;        // 2 M groups of 64
    const int wn = wid >> 1;       // 4 N groups of 32
    const int q = l >> 2, tl = l & 3;

    // ldmatrix lane byte offsets within a 128B-row tile
    // A (m16k16): bit3 -> +8 rows, bit4 -> +16B k-chunk
    const int laneA = ((l & 7) + ((l >> 3) & 1) * 8) * 128 + ((l >> 4) & 1) * 16;
    // B (n16k16): bit4 -> +8 rows, bit3 -> +16B k-chunk
    const int laneB = ((l & 7) + ((l >> 4) & 1) * 8) * 128 + ((l >> 3) & 1) * 16;

    float acc[4][4][4];
    if (LOADC) {
#pragma unroll
        for (int mt = 0; mt < 4; mt++)
#pragma unroll
            for (int nt = 0; nt < 4; nt++) {
                long long r0 = m0 + wm * 64 + mt * 16 + q;
                long long col = n0 + wn * 32 + nt * 8 + tl * 2;
                float2 u0 = *reinterpret_cast<const float2*>(Cin_ + r0 * ldc + col);
                float2 u1 = *reinterpret_cast<const float2*>(Cin_ + (r0 + 8) * ldc + col);
                acc[mt][nt][0] = u0.x; acc[mt][nt][1] = u0.y;
                acc[mt][nt][2] = u1.x; acc[mt][nt][3] = u1.y;
            }
    } else {
#pragma unroll
        for (int i = 0; i < 4; i++)
#pragma unroll
            for (int j = 0; j < 4; j++)
#pragma unroll
                for (int v = 0; v < 4; v++) acc[i][j][v] = 0.f;
    }

    // row layout: [32 hi fp16 | 32 lo fp16] = 128B, SW128 swizzled
    auto load_chunk = [&](int stage, int kt) {
        const long long k0 = (long long)kt << 5;
        const uint32_t st = sb + stage * ST_BYTES;
        if (TERMS == 3) {
#pragma unroll
            for (int i = 0; i < 4; i++) {        // A hi+lo: 1024 16B chunks
                int ch = tid + (i << 8);
                int r = ch >> 3, c = ch & 7;
                const h16* base = (c < 4) ? Ahi : Alo;
                cp16(st + SW128(r * 128 + c * 16),
                     base + (m0 + r) * lda + k0 + (c & 3) * 8);
            }
        } else {
#pragma unroll
            for (int i = 0; i < 2; i++) {        // A hi only: 512 16B chunks
                int ch = tid + (i << 8);
                int r = ch >> 2, c = ch & 3;
                cp16(st + SW128(r * 128 + c * 16),
                     Ahi + (m0 + r) * lda + k0 + c * 8);
            }
        }
#pragma unroll
        for (int i = 0; i < 4; i++) {            // B hi+lo: 1024 16B chunks
            int ch = tid + (i << 8);
            int r = ch >> 3, c = ch & 7;
            const h16* base = (c < 4) ? Bhi : Blo;
            cp16(st + 16384 + SW128(r * 128 + c * 16),
                 base + (n0 + r) * ldb + k0 + (c & 3) * 8);
        }
        CP_COMMIT();
    };

    constexpr int KT = K >> 5;
    load_chunk(0, 0);
    load_chunk(1, 1);
    int s = 0, ls = 2;
#pragma unroll 1
    for (int kt = 0; kt < KT; kt++) {
        // wait for chunk kt's data, then ONE barrier
        if (kt + 1 < KT) { CP_WAIT(1); } else { CP_WAIT(0); }
        __syncthreads();
        // issue next load AFTER the barrier: stage (kt+2)%3 == stage (kt-1)%3
        if (kt + 2 < KT) {
            load_chunk(ls, kt + 2);
            ls = (ls == 2) ? 0 : ls + 1;
        }

        const uint32_t aB = sb + s * ST_BYTES;
        const uint32_t bB = aB + 16384;
#pragma unroll
        for (int kk = 0; kk < 2; kk++) {
            uint32_t Bh[2][4], Bl[2][4];
#pragma unroll
            for (int pt = 0; pt < 2; pt++) {
                int off = (wn * 32 + pt * 16) * 128 + kk * 32 + laneB;
                ldsm4(Bh[pt], bB + SW128(off));        // hi half of row
                ldsm4(Bl[pt], bB + SW128(off + 64));   // lo half of row
            }
#pragma unroll
            for (int mt = 0; mt < 4; mt++) {
                int offA = (wm * 64 + mt * 16) * 128 + kk * 32 + laneA;
                uint32_t Ah[4];
                ldsm4(Ah, aB + SW128(offA));
#pragma unroll
                for (int j = 0; j < 4; j++) {
                    float* c = acc[mt][j];
                    mma16816(c, Ah, &Bh[j >> 1][(j & 1) * 2]);
                    mma16816(c, Ah, &Bl[j >> 1][(j & 1) * 2]);
                }
                if (TERMS == 3) {
                    uint32_t Al[4];
                    ldsm4(Al, aB + SW128(offA + 64));
#pragma unroll
                    for (int j = 0; j < 4; j++)
                        mma16816(acc[mt][j], Al, &Bh[j >> 1][(j & 1) * 2]);
                }
            }
        }
        s = (s == 2) ? 0 : s + 1;
    }

    // ---------------- epilogue ----------------
    float* C = C_ + bz * sC;
    h16* Ph = Phi_ + bz * sP;
    h16* Pl = Plo_ + bz * sP;
#pragma unroll
    for (int mt = 0; mt < 4; mt++) {
#pragma unroll
        for (int nt = 0; nt < 4; nt++) {
            long long r0 = m0 + wm * 64 + mt * 16 + q;
            long long col = n0 + wn * 32 + nt * 8 + tl * 2;
            float d0 = acc[mt][nt][0], d1 = acc[mt][nt][1];
            float d2 = acc[mt][nt][2], d3 = acc[mt][nt][3];
            if (WTANH) { d0 = tanhf(d0); d1 = tanhf(d1); d2 = tanhf(d2); d3 = tanhf(d3); }
            if (WF32) {
                *reinterpret_cast<float2*>(C + r0 * ldc + col)       = make_float2(d0, d1);
                *reinterpret_cast<float2*>(C + (r0 + 8) * ldc + col) = make_float2(d2, d3);
            }
            if (WPAIR) {
                if (WLO) {
                    __half2 H, L;
                    split2(d0, d1, H, L);
                    *reinterpret_cast<__half2*>(Ph + r0 * ldp + col) = H;
                    *reinterpret_cast<__half2*>(Pl + r0 * ldp + col) = L;
                    split2(d2, d3, H, L);
                    *reinterpret_cast<__half2*>(Ph + (r0 + 8) * ldp + col) = H;
                    *reinterpret_cast<__half2*>(Pl + (r0 + 8) * ldp + col) = L;
                } else {
                    *reinterpret_cast<__half2*>(Ph + r0 * ldp + col)       = pack2(d0, d1);
                    *reinterpret_cast<__half2*>(Ph + (r0 + 8) * ldp + col) = pack2(d2, d3);
                }
            }
        }
    }
}

// ---------------- fp32 -> (hi,lo) fp16 split ----------------
__global__ void __launch_bounds__(256) split_kernel(const float* __restrict__ src,
                                                    h16* __restrict__ hi,
                                                    h16* __restrict__ lo, long long n)
{
    long long i4 = ((long long)blockIdx.x * 256 + threadIdx.x) * 4;
    if (i4 >= n) return;
    float4 v = *reinterpret_cast<const float4*>(src + i4);
    __half2 H0, L0, H1, L1;
    split2(v.x, v.y, H0, L0);
    split2(v.z, v.w, H1, L1);
    *reinterpret_cast<__half2*>(hi + i4)     = H0;
    *reinterpret_cast<__half2*>(hi + i4 + 2) = H1;
    *reinterpret_cast<__half2*>(lo + i4)     = L0;
    *reinterpret_cast<__half2*>(lo + i4 + 2) = L1;
}

// ------ fused: input -> (in_hi,in_lo) [B,T,D] + concat fp32 + cc_hi (second half) ------
__global__ void __launch_bounds__(256) input_prep_kernel(const float* __restrict__ in,
                                                         h16* __restrict__ ihi,
                                                         h16* __restrict__ ilo,
                                                         float* __restrict__ concat,
                                                         h16* __restrict__ chi)
{
    const long long DQ = DD / 4;
    long long g = (long long)blockIdx.x * blockDim.x + threadIdx.x;
    long long b   = g / (TD * DQ);
    long long rem = g - b * (TD * DQ);
    long long t   = rem / DQ;
    long long dq  = rem - t * DQ;
    float4 v = reinterpret_cast<const float4*>(in)[g];

    __half2 H0, L0, H1, L1;
    split2(v.x, v.y, H0, L0);
    split2(v.z, v.w, H1, L1);

    const size_t si = (size_t)g * 4;  // [B,T,D] layout
    *reinterpret_cast<__half2*>(ihi + si)     = H0;
    *reinterpret_cast<__half2*>(ihi + si + 2) = H1;
    *reinterpret_cast<__half2*>(ilo + si)     = L0;
    *reinterpret_cast<__half2*>(ilo + si + 2) = L1;

    long long dstq = ((t * BD + b) * (2 * DD) + DD) / 4 + dq;
    reinterpret_cast<float4*>(concat)[dstq] = v;
    const size_t e = (size_t)dstq * 4;
    *reinterpret_cast<__half2*>(chi + e)     = H0;
    *reinterpret_cast<__half2*>(chi + e + 2) = H1;
}

// -------- context transpose + split: ctxT[b,d,s] = ctx[b,s,d] --------
__global__ void __launch_bounds__(256) transpose_split_kernel(const float* __restrict__ ctx,
                                                              h16* __restrict__ tHi,
                                                              h16* __restrict__ tLo)
{
    __shared__ float tile[32][33];
    const int b = blockIdx.z;
    const int d0 = blockIdx.x * 32, s0 = blockIdx.y * 32;
    const int tx = threadIdx.x & 31, ty = threadIdx.x >> 5;
    const float* src = ctx + (size_t)b * SD * DD;
#pragma unroll
    for (int j = 0; j < 4; j++)
        tile[ty + j * 8][tx] = src[(size_t)(s0 + ty + j * 8) * DD + d0 + tx];
    __syncthreads();
    h16* dh = tHi + (size_t)b * DD * SD;
    h16* dl = tLo + (size_t)b * DD * SD;
#pragma unroll
    for (int j = 0; j < 4; j++) {
        float v = tile[tx][ty + j * 8];
        __half h = __float2half_rn(v);
        dh[(size_t)(d0 + ty + j * 8) * SD + s0 + tx] = h;
        dl[(size_t)(d0 + ty + j * 8) * SD + s0 + tx] =
            __float2half_rn(v - __half2float(h));
    }
}

// ---------------- softmax (rows of 1024) + fp16 hi emit ----------------
__global__ void __launch_bounds__(256) softmax1024(float* __restrict__ p,
                                                   h16* __restrict__ hi)
{
    __shared__ float red[8];
    const long long row = blockIdx.x;
    float* r = p + row * 1024;
    const int tid = threadIdx.x;
    float4 v = reinterpret_cast<float4*>(r)[tid];

    float m = fmaxf(fmaxf(v.x, v.y), fmaxf(v.z, v.w));
#pragma unroll
    for (int o = 16; o > 0; o >>= 1) m = fmaxf(m, __shfl_xor_sync(0xffffffffu, m, o));
    if ((tid & 31) == 0) red[tid >> 5] = m;
    __syncthreads();
    float bm = red[0];
#pragma unroll
    for (int i = 1; i < 8; i++) bm = fmaxf(bm, red[i]);
    __syncthreads();

    v.x = __expf(v.x - bm); v.y = __expf(v.y - bm);
    v.z = __expf(v.z - bm); v.w = __expf(v.w - bm);
    float s = v.x + v.y + v.z + v.w;
#pragma unroll
    for (int o = 16; o > 0; o >>= 1) s += __shfl_xor_sync(0xffffffffu, s, o);
    if ((tid & 31) == 0) red[tid >> 5] = s;
    __syncthreads();
    float bs = 0.f;
#pragma unroll
    for (int i = 0; i < 8; i++) bs += red[i];
    const float inv = 1.0f / bs;
    v.x *= inv; v.y *= inv; v.z *= inv; v.w *= inv;
    reinterpret_cast<float4*>(r)[tid] = v;

    const size_t off = (size_t)row * 1024 + tid * 4;
    *reinterpret_cast<__half2*>(hi + off)     = pack2(v.x, v.y);
    *reinterpret_cast<__half2*>(hi + off + 2) = pack2(v.z, v.w);
}

// ---------------- stream/event singletons (created at static init; no device allocs) ----------------
struct GA_Streams {
    cudaStream_t s2;
    cudaEvent_t evRoot, evIn, evCtx, ev6a;
    GA_Streams() {
        int pLow = 0, pHigh = 0;
        cudaDeviceGetStreamPriorityRange(&pLow, &pHigh);
        cudaStreamCreateWithPriority(&s2, cudaStreamNonBlocking, pLow);  // least priority
        cudaEventCreateWithFlags(&evRoot, cudaEventDisableTiming);
        cudaEventCreateWithFlags(&evIn,   cudaEventDisableTiming);
        cudaEventCreateWithFlags(&evCtx,  cudaEventDisableTiming);
        cudaEventCreateWithFlags(&ev6a,   cudaEventDisableTiming);
    }
};
static GA_Streams g_st;

extern "C" void kernel_launch(void* const* d_in, const int* in_sizes, int n_in,
                              void* d_out, int out_size)
{
    (void)in_sizes; (void)n_in; (void)out_size;
    const float* input   = (const float*)d_in[0];   // [B,T,D]
    const float* context = (const float*)d_in[1];   // [B,S,D]
    const float* W_in    = (const float*)d_in[2];   // [D,D]
    const float* W_out   = (const float*)d_in[3];   // [D,2D]

    float* out    = (float*)d_out;
    float* attn   = out;                                   // [T,B,D]
    float* alignv = out + (long long)TD * BD * DD;         // [T,B,S]
    float* concat = alignv + (long long)TD * BD * SD;      // [T,B,2D]

    h16 *in_hi, *in_lo, *ctx_hi, *ctx_lo, *ctxT_hi, *ctxT_lo;
    h16 *win_hi, *win_lo, *wout_hi, *wout_lo;
    h16 *h_hi, *h_lo, *av_hi, *cc_hi;
    float* cbuf;
    cudaGetSymbolAddress((void**)&in_hi,  g_in_hi);   cudaGetSymbolAddress((void**)&in_lo,  g_in_lo);
    cudaGetSymbolAddress((void**)&ctx_hi, g_ctx_hi);  cudaGetSymbolAddress((void**)&ctx_lo, g_ctx_lo);
    cudaGetSymbolAddress((void**)&ctxT_hi,g_ctxT_hi); cudaGetSymbolAddress((void**)&ctxT_lo,g_ctxT_lo);
    cudaGetSymbolAddress((void**)&win_hi, g_win_hi);  cudaGetSymbolAddress((void**)&win_lo, g_win_lo);
    cudaGetSymbolAddress((void**)&wout_hi,g_wout_hi); cudaGetSymbolAddress((void**)&wout_lo,g_wout_lo);
    cudaGetSymbolAddress((void**)&h_hi,   g_h_hi);    cudaGetSymbolAddress((void**)&h_lo,   g_h_lo);
    cudaGetSymbolAddress((void**)&av_hi,  g_av_hi);
    cudaGetSymbolAddress((void**)&cc_hi,  g_cc_hi);
    cudaGetSymbolAddress((void**)&cbuf,   g_cbuf);

    cudaFuncSetAttribute(gemm_hmma<3, 1024, false, false, true,  true,  false>,
                         cudaFuncAttributeMaxDynamicSharedMemorySize, SMEM_TOT);
    cudaFuncSetAttribute(gemm_hmma<3, 1024, true, false, false, false, false>,
                         cudaFuncAttributeMaxDynamicSharedMemorySize, SMEM_TOT);
    cudaFuncSetAttribute(gemm_hmma<2, 1024, true, false, false, false, false>,
                         cudaFuncAttributeMaxDynamicSharedMemorySize, SMEM_TOT);
    cudaFuncSetAttribute(gemm_hmma<2, 1024, true, false, true,  false, false>,
                         cudaFuncAttributeMaxDynamicSharedMemorySize, SMEM_TOT);
    cudaFuncSetAttribute(gemm_hmma<2, 1024, true, true,  false, false, true>,
                         cudaFuncAttributeMaxDynamicSharedMemorySize, SMEM_TOT);

    cudaStream_t s2 = g_st.s2;

    // ---- fork root ----
    cudaEventRecord(g_st.evRoot, 0);
    cudaStreamWaitEvent(s2, g_st.evRoot, 0);

    // ---- main stream: W_in split + input prep, then critical GEMM chain ----
    split_kernel<<<(DD * DD) / 1024, 256>>>(W_in, win_hi, win_lo, (long long)DD * DD);
    input_prep_kernel<<<(BD * TD * DD / 4) / 256, 256>>>(input, in_hi, in_lo, concat, cc_hi);
    cudaEventRecord(g_st.evIn, 0);

    // ---- s2 (least priority): ctx conversions, wout split, then GEMM6a ----
    split_kernel<<<(BD * SD * DD) / 1024, 256, 0, s2>>>(context, ctx_hi, ctx_lo,
                                                        (long long)BD * SD * DD);
    split_kernel<<<(DD * 2 * DD) / 1024, 256, 0, s2>>>(W_out, wout_hi, wout_lo,
                                                       (long long)DD * 2 * DD);
    transpose_split_kernel<<<dim3(DD / 32, SD / 32, BD), 256, 0, s2>>>(context, ctxT_hi, ctxT_lo);
    cudaEventRecord(g_st.evCtx, s2);
    cudaStreamWaitEvent(s2, g_st.evIn, 0);
    // GEMM6a: cbuf = input @ Wout_i^T  (A = cc second half hi, B = W_out cols [1024:2048))
    gemm_hmma<2, 1024, true, false, false, false, false>
        <<<dim3(DD / 128, (TD * BD) / 128, 1), 256, SMEM_TOT, s2>>>(
        cc_hi + DD, nullptr, 2 * DD, 0LL,
        wout_hi + DD, wout_lo + DD, 2 * DD, 0LL,
        cbuf, DD, 0LL, nullptr, nullptr, 0LL, 0LL, nullptr);
    cudaEventRecord(g_st.ev6a, s2);

    // 1) h = input @ W_in^T : K=1024 -> (h_hi, h_lo)  (3-term: feeds logits)
    gemm_hmma<3, 1024, false, false, true, true, false>
        <<<dim3(DD / 128, (BD * TD) / 128, 1), 256, SMEM_TOT>>>(
        in_hi, in_lo, DD, 0LL, win_hi, win_lo, DD, 0LL,
        nullptr, 0LL, 0LL, h_hi, h_lo, DD, 0LL, nullptr);

    // 2) align[b] = h[b] @ ctx[b]^T : K=1024 -> fp32 into [T,B,S]  (3-term: logits)
    cudaStreamWaitEvent(0, g_st.evCtx, 0);
    gemm_hmma<3, 1024, true, false, false, false, false>
        <<<dim3(SD / 128, TD / 128, BD), 256, SMEM_TOT>>>(
        h_hi, h_lo, DD, (long long)TD * DD, ctx_hi, ctx_lo, DD, (long long)SD * DD,
        alignv, (long long)BD * SD, (long long)SD, nullptr, nullptr, 0LL, 0LL, nullptr);

    // 3) softmax over S + fp16 hi
    softmax1024<<<TD * BD, 256>>>(alignv, av_hi);

    // 4) c[b] = av[b] @ ctxT[b]^T : K=1024(S) -> fp32 + cc_hi  (2-term, A-hi only)
    gemm_hmma<2, 1024, true, false, true, false, false>
        <<<dim3(DD / 128, TD / 128, BD), 256, SMEM_TOT>>>(
        av_hi, nullptr, (long long)BD * SD, (long long)SD,
        ctxT_hi, ctxT_lo, SD, (long long)DD * SD,
        concat, (long long)BD * 2 * DD, (long long)(2 * DD),
        cc_hi, nullptr, (long long)BD * 2 * DD, (long long)(2 * DD), nullptr);

    // 5) attn = tanh(cbuf + c @ Wout_c^T) : K=1024, acc init from cbuf  (2-term)
    cudaStreamWaitEvent(0, g_st.ev6a, 0);
    gemm_hmma<2, 1024, true, true, false, false, true>
        <<<dim3(DD / 128, (TD * BD) / 128, 1), 256, SMEM_TOT>>>(
        cc_hi, nullptr, 2 * DD, 0LL, wout_hi, wout_lo, 2 * DD, 0LL,
        attn, DD, 0LL, nullptr, nullptr, 0LL, 0LL, cbuf);
}

// round 13
// speedup vs baseline: 1.5196x; 1.5196x over previous
#include <cuda_runtime.h>
#include <cuda_fp16.h>
#include <cstdint>
#include <math.h>

#define BD 32
#define TD 512
#define SD 1024
#define DD 1024

typedef __half h16;

// ---------------- scratch (device globals; no runtime allocation) ----------------
__device__ h16 g_in_hi [(size_t)BD*TD*DD],   g_in_lo [(size_t)BD*TD*DD];
__device__ h16 g_ctx_hi[(size_t)BD*SD*DD],   g_ctx_lo[(size_t)BD*SD*DD];
__device__ h16 g_ctxT_hi[(size_t)BD*DD*SD],  g_ctxT_lo[(size_t)BD*DD*SD];
__device__ h16 g_win_hi[(size_t)DD*DD],      g_win_lo[(size_t)DD*DD];
__device__ h16 g_wout_hi[(size_t)DD*2*DD],   g_wout_lo[(size_t)DD*2*DD];
__device__ h16 g_h_hi  [(size_t)BD*TD*DD],   g_h_lo  [(size_t)BD*TD*DD];
__device__ h16 g_av_hi [(size_t)TD*BD*SD];
__device__ h16 g_cc_hi [(size_t)TD*BD*2*DD];
__device__ float g_cbuf[(size_t)TD*BD*DD];   // GEMM6a partial (input @ Wout_i^T)

// ---------------- PTX helpers ----------------
__device__ __forceinline__ uint32_t smem_u32(const void* p) {
    uint32_t a;
    asm("{ .reg .u64 t; cvta.to.shared.u64 t, %1; cvt.u32.u64 %0, t; }" : "=r"(a) : "l"(p));
    return a;
}
__device__ __forceinline__ void cp16(uint32_t dst, const void* src) {
    asm volatile("cp.async.cg.shared.global [%0], [%1], 16;\n" :: "r"(dst), "l"(src) : "memory");
}
#define CP_COMMIT() asm volatile("cp.async.commit_group;\n" ::: "memory")
#define CP_WAIT(n)  asm volatile("cp.async.wait_group %0;\n" :: "n"(n) : "memory")
#define SW128(o)    ((o) ^ (((o) >> 3) & 0x70))

__device__ __forceinline__ void ldsm4(uint32_t* r, uint32_t addr) {
    asm volatile("ldmatrix.sync.aligned.m8n8.x4.shared.b16 {%0,%1,%2,%3}, [%4];"
                 : "=r"(r[0]), "=r"(r[1]), "=r"(r[2]), "=r"(r[3]) : "r"(addr));
}
__device__ __forceinline__ void mma16816(float* c, const uint32_t* a, const uint32_t* b) {
    asm volatile(
        "mma.sync.aligned.m16n8k16.row.col.f32.f16.f16.f32 "
        "{%0,%1,%2,%3}, {%4,%5,%6,%7}, {%8,%9}, {%0,%1,%2,%3};"
        : "+f"(c[0]), "+f"(c[1]), "+f"(c[2]), "+f"(c[3])
        : "r"(a[0]), "r"(a[1]), "r"(a[2]), "r"(a[3]), "r"(b[0]), "r"(b[1]));
}
__device__ __forceinline__ void split2(float a, float b, __half2& H, __half2& L) {
    __half ha = __float2half_rn(a), hb = __float2half_rn(b);
    H = __halves2half2(ha, hb);
    L = __halves2half2(__float2half_rn(a - __half2float(ha)),
                       __float2half_rn(b - __half2float(hb)));
}
__device__ __forceinline__ __half2 pack2(float a, float b) {
    return __halves2half2(__float2half_rn(a), __float2half_rn(b));
}

// ---------------- fp16-split HMMA GEMM, occupancy-2, single-sync mainloop ----------------
// C[m,n] = sum_k A[m,k]*B[n,k] (NT). B fp16 (hi,lo) pair of fp32.
// TERMS=3: A (hi,lo) pair, Ah*Bh + Ah*Bl + Al*Bh.  TERMS=2: A hi only, Ah*(Bh+Bl).
// CTA 128x128, warp tile 64x32 (8 warps as 2Mx4N). K-chunk 32, [hi|lo] packed per
// 128B row; stage 32KB; 3-stage cp.async pipeline; 2 CTAs/SM. LOADC: acc init Cin.
// WPAIR: emit fp16 hi; WLO additionally emit fp16 lo (fp32 residual).
static constexpr int ST_BYTES = 32768;           // A 16K (hi|lo slots) + B 16K
static constexpr int SMEM_TOT = 3 * ST_BYTES;    // 96 KB -> 2 CTAs/SM

template <int TERMS, int K, bool WF32, bool WTANH, bool WPAIR, bool WLO, bool LOADC>
__global__ void __launch_bounds__(256, 2) gemm_hmma(
    const h16* __restrict__ Ahi_, const h16* __restrict__ Alo_,
    long long lda, long long sA,
    const h16* __restrict__ Bhi_, const h16* __restrict__ Blo_,
    long long ldb, long long sB,
    float* __restrict__ C_, long long ldc, long long sC,
    h16* __restrict__ Phi_, h16* __restrict__ Plo_,
    long long ldp, long long sP,
    const float* __restrict__ Cin_)
{
    extern __shared__ char smem[];
    const uint32_t sb = smem_u32(smem);
    const int tid = threadIdx.x, wid = tid >> 5, l = tid & 31;
    const long long bz = blockIdx.z;
    const h16* Ahi = Ahi_ + bz * sA;
    const h16* Alo = Alo_ + bz * sA;
    const h16* Bhi = Bhi_ + bz * sB;
    const h16* Blo = Blo_ + bz * sB;
    const long long m0 = (long long)blockIdx.y * 128;
    const long long n0 = (long long)blockIdx.x * 128;

    const int wm = wid & 1;        // 2 M groups of 64
    const int wn = wid >> 1;       // 4 N groups of 32
    const int q = l >> 2, tl = l & 3;

    // ldmatrix lane byte offsets within a 128B-row tile
    // A (m16k16): bit3 -> +8 rows, bit4 -> +16B k-chunk
    const int laneA = ((l & 7) + ((l >> 3) & 1) * 8) * 128 + ((l >> 4) & 1) * 16;
    // B (n16k16): bit4 -> +8 rows, bit3 -> +16B k-chunk
    const int laneB = ((l & 7) + ((l >> 4) & 1) * 8) * 128 + ((l >> 3) & 1) * 16;

    float acc[4][4][4];
    if (LOADC) {
#pragma unroll
        for (int mt = 0; mt < 4; mt++)
#pragma unroll
            for (int nt = 0; nt < 4; nt++) {
                long long r0 = m0 + wm * 64 + mt * 16 + q;
                long long col = n0 + wn * 32 + nt * 8 + tl * 2;
                float2 u0 = *reinterpret_cast<const float2*>(Cin_ + r0 * ldc + col);
                float2 u1 = *reinterpret_cast<const float2*>(Cin_ + (r0 + 8) * ldc + col);
                acc[mt][nt][0] = u0.x; acc[mt][nt][1] = u0.y;
                acc[mt][nt][2] = u1.x; acc[mt][nt][3] = u1.y;
            }
    } else {
#pragma unroll
        for (int i = 0; i < 4; i++)
#pragma unroll
            for (int j = 0; j < 4; j++)
#pragma unroll
                for (int v = 0; v < 4; v++) acc[i][j][v] = 0.f;
    }

    // row layout: [32 hi fp16 | 32 lo fp16] = 128B, SW128 swizzled
    auto load_chunk = [&](int stage, int kt) {
        const long long k0 = (long long)kt << 5;
        const uint32_t st = sb + stage * ST_BYTES;
        if (TERMS == 3) {
#pragma unroll
            for (int i = 0; i < 4; i++) {        // A hi+lo: 1024 16B chunks
                int ch = tid + (i << 8);
                int r = ch >> 3, c = ch & 7;
                const h16* base = (c < 4) ? Ahi : Alo;
                cp16(st + SW128(r * 128 + c * 16),
                     base + (m0 + r) * lda + k0 + (c & 3) * 8);
            }
        } else {
#pragma unroll
            for (int i = 0; i < 2; i++) {        // A hi only: 512 16B chunks
                int ch = tid + (i << 8);
                int r = ch >> 2, c = ch & 3;
                cp16(st + SW128(r * 128 + c * 16),
                     Ahi + (m0 + r) * lda + k0 + c * 8);
            }
        }
#pragma unroll
        for (int i = 0; i < 4; i++) {            // B hi+lo: 1024 16B chunks
            int ch = tid + (i << 8);
            int r = ch >> 3, c = ch & 7;
            const h16* base = (c < 4) ? Bhi : Blo;
            cp16(st + 16384 + SW128(r * 128 + c * 16),
                 base + (n0 + r) * ldb + k0 + (c & 3) * 8);
        }
        CP_COMMIT();
    };

    constexpr int KT = K >> 5;
    load_chunk(0, 0);
    load_chunk(1, 1);
    int s = 0, ls = 2;
#pragma unroll 1
    for (int kt = 0; kt < KT; kt++) {
        // wait for chunk kt's data, then ONE barrier
        if (kt + 1 < KT) { CP_WAIT(1); } else { CP_WAIT(0); }
        __syncthreads();
        // issue next load AFTER the barrier: stage (kt+2)%3 == stage (kt-1)%3
        if (kt + 2 < KT) {
            load_chunk(ls, kt + 2);
            ls = (ls == 2) ? 0 : ls + 1;
        }

        const uint32_t aB = sb + s * ST_BYTES;
        const uint32_t bB = aB + 16384;
#pragma unroll
        for (int kk = 0; kk < 2; kk++) {
            uint32_t Bh[2][4], Bl[2][4];
#pragma unroll
            for (int pt = 0; pt < 2; pt++) {
                int off = (wn * 32 + pt * 16) * 128 + kk * 32 + laneB;
                ldsm4(Bh[pt], bB + SW128(off));        // hi half of row
                ldsm4(Bl[pt], bB + SW128(off + 64));   // lo half of row
            }
#pragma unroll
            for (int mt = 0; mt < 4; mt++) {
                int offA = (wm * 64 + mt * 16) * 128 + kk * 32 + laneA;
                uint32_t Ah[4];
                ldsm4(Ah, aB + SW128(offA));
#pragma unroll
                for (int j = 0; j < 4; j++) {
                    float* c = acc[mt][j];
                    mma16816(c, Ah, &Bh[j >> 1][(j & 1) * 2]);
                    mma16816(c, Ah, &Bl[j >> 1][(j & 1) * 2]);
                }
                if (TERMS == 3) {
                    uint32_t Al[4];
                    ldsm4(Al, aB + SW128(offA + 64));
#pragma unroll
                    for (int j = 0; j < 4; j++)
                        mma16816(acc[mt][j], Al, &Bh[j >> 1][(j & 1) * 2]);
                }
            }
        }
        s = (s == 2) ? 0 : s + 1;
    }

    // ---------------- epilogue ----------------
    float* C = C_ + bz * sC;
    h16* Ph = Phi_ + bz * sP;
    h16* Pl = Plo_ + bz * sP;
#pragma unroll
    for (int mt = 0; mt < 4; mt++) {
#pragma unroll
        for (int nt = 0; nt < 4; nt++) {
            long long r0 = m0 + wm * 64 + mt * 16 + q;
            long long col = n0 + wn * 32 + nt * 8 + tl * 2;
            float d0 = acc[mt][nt][0], d1 = acc[mt][nt][1];
            float d2 = acc[mt][nt][2], d3 = acc[mt][nt][3];
            if (WTANH) { d0 = tanhf(d0); d1 = tanhf(d1); d2 = tanhf(d2); d3 = tanhf(d3); }
            if (WF32) {
                *reinterpret_cast<float2*>(C + r0 * ldc + col)       = make_float2(d0, d1);
                *reinterpret_cast<float2*>(C + (r0 + 8) * ldc + col) = make_float2(d2, d3);
            }
            if (WPAIR) {
                if (WLO) {
                    __half2 H, L;
                    split2(d0, d1, H, L);
                    *reinterpret_cast<__half2*>(Ph + r0 * ldp + col) = H;
                    *reinterpret_cast<__half2*>(Pl + r0 * ldp + col) = L;
                    split2(d2, d3, H, L);
                    *reinterpret_cast<__half2*>(Ph + (r0 + 8) * ldp + col) = H;
                    *reinterpret_cast<__half2*>(Pl + (r0 + 8) * ldp + col) = L;
                } else {
                    *reinterpret_cast<__half2*>(Ph + r0 * ldp + col)       = pack2(d0, d1);
                    *reinterpret_cast<__half2*>(Ph + (r0 + 8) * ldp + col) = pack2(d2, d3);
                }
            }
        }
    }
}

// ---------------- fp32 -> (hi,lo) fp16 split ----------------
__global__ void __launch_bounds__(256) split_kernel(const float* __restrict__ src,
                                                    h16* __restrict__ hi,
                                                    h16* __restrict__ lo, long long n)
{
    long long i4 = ((long long)blockIdx.x * 256 + threadIdx.x) * 4;
    if (i4 >= n) return;
    float4 v = *reinterpret_cast<const float4*>(src + i4);
    __half2 H0, L0, H1, L1;
    split2(v.x, v.y, H0, L0);
    split2(v.z, v.w, H1, L1);
    *reinterpret_cast<__half2*>(hi + i4)     = H0;
    *reinterpret_cast<__half2*>(hi + i4 + 2) = H1;
    *reinterpret_cast<__half2*>(lo + i4)     = L0;
    *reinterpret_cast<__half2*>(lo + i4 + 2) = L1;
}

// ------ fused: input -> (in_hi,in_lo) [B,T,D] + concat fp32 + cc_hi (second half) ------
__global__ void __launch_bounds__(256) input_prep_kernel(const float* __restrict__ in,
                                                         h16* __restrict__ ihi,
                                                         h16* __restrict__ ilo,
                                                         float* __restrict__ concat,
                                                         h16* __restrict__ chi)
{
    const long long DQ = DD / 4;
    long long g = (long long)blockIdx.x * blockDim.x + threadIdx.x;
    long long b   = g / (TD * DQ);
    long long rem = g - b * (TD * DQ);
    long long t   = rem / DQ;
    long long dq  = rem - t * DQ;
    float4 v = reinterpret_cast<const float4*>(in)[g];

    __half2 H0, L0, H1, L1;
    split2(v.x, v.y, H0, L0);
    split2(v.z, v.w, H1, L1);

    const size_t si = (size_t)g * 4;  // [B,T,D] layout
    *reinterpret_cast<__half2*>(ihi + si)     = H0;
    *reinterpret_cast<__half2*>(ihi + si + 2) = H1;
    *reinterpret_cast<__half2*>(ilo + si)     = L0;
    *reinterpret_cast<__half2*>(ilo + si + 2) = L1;

    long long dstq = ((t * BD + b) * (2 * DD) + DD) / 4 + dq;
    reinterpret_cast<float4*>(concat)[dstq] = v;
    const size_t e = (size_t)dstq * 4;
    *reinterpret_cast<__half2*>(chi + e)     = H0;
    *reinterpret_cast<__half2*>(chi + e + 2) = H1;
}

// -------- context transpose + split: ctxT[b,d,s] = ctx[b,s,d] --------
__global__ void __launch_bounds__(256) transpose_split_kernel(const float* __restrict__ ctx,
                                                              h16* __restrict__ tHi,
                                                              h16* __restrict__ tLo)
{
    __shared__ float tile[32][33];
    const int b = blockIdx.z;
    const int d0 = blockIdx.x * 32, s0 = blockIdx.y * 32;
    const int tx = threadIdx.x & 31, ty = threadIdx.x >> 5;
    const float* src = ctx + (size_t)b * SD * DD;
#pragma unroll
    for (int j = 0; j < 4; j++)
        tile[ty + j * 8][tx] = src[(size_t)(s0 + ty + j * 8) * DD + d0 + tx];
    __syncthreads();
    h16* dh = tHi + (size_t)b * DD * SD;
    h16* dl = tLo + (size_t)b * DD * SD;
#pragma unroll
    for (int j = 0; j < 4; j++) {
        float v = tile[tx][ty + j * 8];
        __half h = __float2half_rn(v);
        dh[(size_t)(d0 + ty + j * 8) * SD + s0 + tx] = h;
        dl[(size_t)(d0 + ty + j * 8) * SD + s0 + tx] =
            __float2half_rn(v - __half2float(h));
    }
}

// ---------------- softmax (rows of 1024) + fp16 hi emit ----------------
__global__ void __launch_bounds__(256) softmax1024(float* __restrict__ p,
                                                   h16* __restrict__ hi)
{
    __shared__ float red[8];
    const long long row = blockIdx.x;
    float* r = p + row * 1024;
    const int tid = threadIdx.x;
    float4 v = reinterpret_cast<float4*>(r)[tid];

    float m = fmaxf(fmaxf(v.x, v.y), fmaxf(v.z, v.w));
#pragma unroll
    for (int o = 16; o > 0; o >>= 1) m = fmaxf(m, __shfl_xor_sync(0xffffffffu, m, o));
    if ((tid & 31) == 0) red[tid >> 5] = m;
    __syncthreads();
    float bm = red[0];
#pragma unroll
    for (int i = 1; i < 8; i++) bm = fmaxf(bm, red[i]);
    __syncthreads();

    v.x = __expf(v.x - bm); v.y = __expf(v.y - bm);
    v.z = __expf(v.z - bm); v.w = __expf(v.w - bm);
    float s = v.x + v.y + v.z + v.w;
#pragma unroll
    for (int o = 16; o > 0; o >>= 1) s += __shfl_xor_sync(0xffffffffu, s, o);
    if ((tid & 31) == 0) red[tid >> 5] = s;
    __syncthreads();
    float bs = 0.f;
#pragma unroll
    for (int i = 0; i < 8; i++) bs += red[i];
    const float inv = 1.0f / bs;
    v.x *= inv; v.y *= inv; v.z *= inv; v.w *= inv;
    reinterpret_cast<float4*>(r)[tid] = v;

    const size_t off = (size_t)row * 1024 + tid * 4;
    *reinterpret_cast<__half2*>(hi + off)     = pack2(v.x, v.y);
    *reinterpret_cast<__half2*>(hi + off + 2) = pack2(v.z, v.w);
}

// ---------------- stream/event singletons (created at static init; no device allocs) ----------------
struct GA_Streams {
    cudaStream_t s2;
    cudaEvent_t evRoot, evIn, evCtx, ev6a;
    GA_Streams() {
        cudaStreamCreateWithFlags(&s2, cudaStreamNonBlocking);  // DEFAULT priority (R10 config)
        cudaEventCreateWithFlags(&evRoot, cudaEventDisableTiming);
        cudaEventCreateWithFlags(&evIn,   cudaEventDisableTiming);
        cudaEventCreateWithFlags(&evCtx,  cudaEventDisableTiming);
        cudaEventCreateWithFlags(&ev6a,   cudaEventDisableTiming);
    }
};
static GA_Streams g_st;

extern "C" void kernel_launch(void* const* d_in, const int* in_sizes, int n_in,
                              void* d_out, int out_size)
{
    (void)in_sizes; (void)n_in; (void)out_size;
    const float* input   = (const float*)d_in[0];   // [B,T,D]
    const float* context = (const float*)d_in[1];   // [B,S,D]
    const float* W_in    = (const float*)d_in[2];   // [D,D]
    const float* W_out   = (const float*)d_in[3];   // [D,2D]

    float* out    = (float*)d_out;
    float* attn   = out;                                   // [T,B,D]
    float* alignv = out + (long long)TD * BD * DD;         // [T,B,S]
    float* concat = alignv + (long long)TD * BD * SD;      // [T,B,2D]

    h16 *in_hi, *in_lo, *ctx_hi, *ctx_lo, *ctxT_hi, *ctxT_lo;
    h16 *win_hi, *win_lo, *wout_hi, *wout_lo;
    h16 *h_hi, *h_lo, *av_hi, *cc_hi;
    float* cbuf;
    cudaGetSymbolAddress((void**)&in_hi,  g_in_hi);   cudaGetSymbolAddress((void**)&in_lo,  g_in_lo);
    cudaGetSymbolAddress((void**)&ctx_hi, g_ctx_hi);  cudaGetSymbolAddress((void**)&ctx_lo, g_ctx_lo);
    cudaGetSymbolAddress((void**)&ctxT_hi,g_ctxT_hi); cudaGetSymbolAddress((void**)&ctxT_lo,g_ctxT_lo);
    cudaGetSymbolAddress((void**)&win_hi, g_win_hi);  cudaGetSymbolAddress((void**)&win_lo, g_win_lo);
    cudaGetSymbolAddress((void**)&wout_hi,g_wout_hi); cudaGetSymbolAddress((void**)&wout_lo,g_wout_lo);
    cudaGetSymbolAddress((void**)&h_hi,   g_h_hi);    cudaGetSymbolAddress((void**)&h_lo,   g_h_lo);
    cudaGetSymbolAddress((void**)&av_hi,  g_av_hi);
    cudaGetSymbolAddress((void**)&cc_hi,  g_cc_hi);
    cudaGetSymbolAddress((void**)&cbuf,   g_cbuf);

    cudaFuncSetAttribute(gemm_hmma<3, 1024, false, false, true,  true,  false>,
                         cudaFuncAttributeMaxDynamicSharedMemorySize, SMEM_TOT);
    cudaFuncSetAttribute(gemm_hmma<3, 1024, true, false, false, false, false>,
                         cudaFuncAttributeMaxDynamicSharedMemorySize, SMEM_TOT);
    cudaFuncSetAttribute(gemm_hmma<2, 1024, true, false, false, false, false>,
                         cudaFuncAttributeMaxDynamicSharedMemorySize, SMEM_TOT);
    cudaFuncSetAttribute(gemm_hmma<2, 1024, true, false, true,  false, false>,
                         cudaFuncAttributeMaxDynamicSharedMemorySize, SMEM_TOT);
    cudaFuncSetAttribute(gemm_hmma<2, 1024, true, true,  false, false, true>,
                         cudaFuncAttributeMaxDynamicSharedMemorySize, SMEM_TOT);

    cudaStream_t s2 = g_st.s2;

    // ---- fork root ----
    cudaEventRecord(g_st.evRoot, 0);
    cudaStreamWaitEvent(s2, g_st.evRoot, 0);

    // ---- main stream: input prep + W_in split, then critical GEMM chain ----
    input_prep_kernel<<<(BD * TD * DD / 4) / 256, 256>>>(input, in_hi, in_lo, concat, cc_hi);
    cudaEventRecord(g_st.evIn, 0);
    split_kernel<<<(DD * DD) / 1024, 256>>>(W_in, win_hi, win_lo, (long long)DD * DD);

    // ---- s2 (default priority): ctx conversions, wout split, then GEMM6a ----
    split_kernel<<<(BD * SD * DD) / 1024, 256, 0, s2>>>(context, ctx_hi, ctx_lo,
                                                        (long long)BD * SD * DD);
    split_kernel<<<(DD * 2 * DD) / 1024, 256, 0, s2>>>(W_out, wout_hi, wout_lo,
                                                       (long long)DD * 2 * DD);
    transpose_split_kernel<<<dim3(DD / 32, SD / 32, BD), 256, 0, s2>>>(context, ctxT_hi, ctxT_lo);
    cudaEventRecord(g_st.evCtx, s2);
    cudaStreamWaitEvent(s2, g_st.evIn, 0);
    // GEMM6a: cbuf = input @ Wout_i^T  (A = cc second half hi, B = W_out cols [1024:2048))
    gemm_hmma<2, 1024, true, false, false, false, false>
        <<<dim3(DD / 128, (TD * BD) / 128, 1), 256, SMEM_TOT, s2>>>(
        cc_hi + DD, nullptr, 2 * DD, 0LL,
        wout_hi + DD, wout_lo + DD, 2 * DD, 0LL,
        cbuf, DD, 0LL, nullptr, nullptr, 0LL, 0LL, nullptr);
    cudaEventRecord(g_st.ev6a, s2);

    // 1) h = input @ W_in^T : K=1024 -> (h_hi, h_lo)  (3-term: feeds logits)
    gemm_hmma<3, 1024, false, false, true, true, false>
        <<<dim3(DD / 128, (BD * TD) / 128, 1), 256, SMEM_TOT>>>(
        in_hi, in_lo, DD, 0LL, win_hi, win_lo, DD, 0LL,
        nullptr, 0LL, 0LL, h_hi, h_lo, DD, 0LL, nullptr);

    // 2) align[b] = h[b] @ ctx[b]^T : K=1024 -> fp32 into [T,B,S]  (3-term: logits)
    cudaStreamWaitEvent(0, g_st.evCtx, 0);
    gemm_hmma<3, 1024, true, false, false, false, false>
        <<<dim3(SD / 128, TD / 128, BD), 256, SMEM_TOT>>>(
        h_hi, h_lo, DD, (long long)TD * DD, ctx_hi, ctx_lo, DD, (long long)SD * DD,
        alignv, (long long)BD * SD, (long long)SD, nullptr, nullptr, 0LL, 0LL, nullptr);

    // 3) softmax over S + fp16 hi
    softmax1024<<<TD * BD, 256>>>(alignv, av_hi);

    // 4) c[b] = av[b] @ ctxT[b]^T : K=1024(S) -> fp32 + cc_hi  (2-term, A-hi only)
    gemm_hmma<2, 1024, true, false, true, false, false>
        <<<dim3(DD / 128, TD / 128, BD), 256, SMEM_TOT>>>(
        av_hi, nullptr, (long long)BD * SD, (long long)SD,
        ctxT_hi, ctxT_lo, SD, (long long)DD * SD,
        concat, (long long)BD * 2 * DD, (long long)(2 * DD),
        cc_hi, nullptr, (long long)BD * 2 * DD, (long long)(2 * DD), nullptr);

    // 5) attn = tanh(cbuf + c @ Wout_c^T) : K=1024, acc init from cbuf  (2-term)
    cudaStreamWaitEvent(0, g_st.ev6a, 0);
    gemm_hmma<2, 1024, true, true, false, false, true>
        <<<dim3(DD / 128, (TD * BD) / 128, 1), 256, SMEM_TOT>>>(
        cc_hi, nullptr, 2 * DD, 0LL, wout_hi, wout_lo, 2 * DD, 0LL,
        attn, DD, 0LL, nullptr, nullptr, 0LL, 0LL, cbuf);
}